// round 6
// baseline (speedup 1.0000x reference)
#include <cuda_runtime.h>
#include <cstdint>

#define NN 50000
#define NE 1600000

// Scratch (static device globals — no allocation in kernel_launch)
__device__ float g_P[NN * 64];     // P[n][j] = fR_b1[j] + sum_k x[n][k] * fR_W1[k][j]      (dst part)
__device__ float g_Q[NN * 64];     // Q[n][j] =            sum_k x[n][k] * fR_W1[16+k][j]   (src part)
__device__ float g_agg[NN * 16];   // scatter-sum of e_new by dst

typedef unsigned long long ull;

__device__ __forceinline__ void ffma2(ull& d, ull a, ull b) {
    asm("fma.rn.f32x2 %0, %1, %2, %0;" : "+l"(d) : "l"(a), "l"(b));
}
__device__ __forceinline__ void fadd2(ull& d, ull a) {
    asm("add.rn.f32x2 %0, %0, %1;" : "+l"(d) : "l"(a));
}
__device__ __forceinline__ ull fdup(float v) {
    ull r; asm("mov.b64 %0, {%1, %1};" : "=l"(r) : "f"(v)); return r;
}
__device__ __forceinline__ ull fpk(float x, float y) {
    ull r; asm("mov.b64 %0, {%1, %2};" : "=l"(r) : "f"(x), "f"(y)); return r;
}
__device__ __forceinline__ float2 unpk(ull v) {
    float2 r; asm("mov.b64 {%0, %1}, %2;" : "=f"(r.x), "=f"(r.y) : "l"(v)); return r;
}

// ---------------------------------------------------------------------------
// K0: zero the aggregation buffer
// ---------------------------------------------------------------------------
__global__ void zero_agg_kernel() {
    int i = blockIdx.x * 256 + threadIdx.x;
    if (i < NN * 16 / 4) ((float4*)g_agg)[i] = make_float4(0.f, 0.f, 0.f, 0.f);
}

// ---------------------------------------------------------------------------
// K1: per-node precompute  P = x@W1[0:16] + b1,  Q = x@W1[16:32]
// ---------------------------------------------------------------------------
__global__ void __launch_bounds__(256) precompute_pq(
    const float* __restrict__ x, const float* __restrict__ W1,
    const float* __restrict__ b1)
{
    int idx = blockIdx.x * 256 + threadIdx.x;       // exactly NN*64 threads
    int n = idx >> 6, j = idx & 63;
    float p = b1[j], q = 0.f;
#pragma unroll
    for (int k = 0; k < 16; k++) {
        float xv = __ldg(x + n * 16 + k);           // broadcast within warp
        p = fmaf(xv, W1[k * 64 + j], p);
        q = fmaf(xv, W1[(16 + k) * 64 + j], q);
    }
    g_P[idx] = p;
    g_Q[idx] = q;
}

// ---------------------------------------------------------------------------
// K2: edge kernel. 128 edges/block, 128 threads (32 edge-rows x 4 col-groups).
//   h[e][j]   = relu( P[dst_e][j] + Q[src_e][j] + sum_k e[e][k] * W1c[k][j] )
//   out[e][c] = b2[c] + sum_j h[e][j] * W2[j][c]
// All GEMM math in packed fp32 (fma.rn.f32x2), edge-pairs in the packed lanes.
// Thread tile: 4 edges x 16 hidden (j = tx*16..tx*16+15).
// ---------------------------------------------------------------------------
__global__ void __launch_bounds__(128) edge_kernel(
    const int* __restrict__ ei, const float* __restrict__ e_in,
    const float* __restrict__ W1, const float* __restrict__ W2,
    const float* __restrict__ b2, float* __restrict__ e_out)
{
    __shared__ int s_src[128], s_dst[128];
    __shared__ __align__(16) float s_ET[16][128];   // e transposed [k][edge]
    __shared__ __align__(16) float s_W1d[16][128];  // W1c rows, each weight duplicated (w,w)
    __shared__ __align__(16) float s_W2[64][16];    // W2 as-is (rows give natural c-pairs)

    const int tid = threadIdx.x;
    const int tx = tid & 3;          // hidden col-group (16 j each)
    const int ty = tid >> 2;         // edge-row (4 edges each)
    const int base = blockIdx.x * 128;

    // ---- stage indices (edge_index is int32: JAX x64-disabled) ----
    s_src[tid] = ei[base + tid];
    s_dst[tid] = ei[NE + base + tid];

    // ---- stage e tile, transposed to [k][edge] (coalesced float4 loads) ----
#pragma unroll
    for (int r = 0; r < 4; r++) {
        int idx = r * 128 + tid;                     // 0..511
        float4 v = ((const float4*)e_in)[base * 4 + idx];
        int edge = idx >> 2, part = idx & 3;
        s_ET[part * 4 + 0][edge] = v.x;
        s_ET[part * 4 + 1][edge] = v.y;
        s_ET[part * 4 + 2][edge] = v.z;
        s_ET[part * 4 + 3][edge] = v.w;
    }
    // ---- stage W1c (rows 32..47 of fR_W1), duplicated for f32x2 ----
#pragma unroll
    for (int r = 0; r < 8; r++) {
        int t = r * 128 + tid;                       // 0..1023
        int k = t >> 6, j = t & 63;
        float w = W1[(32 + k) * 64 + j];
        s_W1d[k][2 * j] = w;
        s_W1d[k][2 * j + 1] = w;
    }
    // ---- stage W2 ----
#pragma unroll
    for (int r = 0; r < 8; r++) {
        int t = r * 128 + tid;
        (&s_W2[0][0])[t] = W2[t];
    }
    __syncthreads();

    // ---- accumulator init: acc[p][jj] packs (edge 2p, edge 2p+1) of P[dst]+Q[src] ----
    ull acc[2][16];
    {
        float vs[4][16];
#pragma unroll
        for (int e2 = 0; e2 < 4; e2++) {
            int d = s_dst[ty * 4 + e2];
            int s = s_src[ty * 4 + e2];
            const float4* Pp = (const float4*)(g_P + d * 64) + tx * 4;
            const float4* Qp = (const float4*)(g_Q + s * 64) + tx * 4;
#pragma unroll
            for (int q = 0; q < 4; q++) {
                float4 pv = Pp[q];
                float4 qv = Qp[q];
                vs[e2][q * 4 + 0] = pv.x + qv.x;
                vs[e2][q * 4 + 1] = pv.y + qv.y;
                vs[e2][q * 4 + 2] = pv.z + qv.z;
                vs[e2][q * 4 + 3] = pv.w + qv.w;
            }
        }
#pragma unroll
        for (int p = 0; p < 2; p++)
#pragma unroll
            for (int jj = 0; jj < 16; jj++)
                acc[p][jj] = fpk(vs[2 * p][jj], vs[2 * p + 1][jj]);
    }

    // ---- GEMM1: += e @ W1c  (16 k-steps, 32 FFMA2 each) ----
#pragma unroll
    for (int k = 0; k < 16; k++) {
        ulonglong2 av = *(const ulonglong2*)&s_ET[k][ty * 4];       // pairs (e0,e1),(e2,e3)
        const ulonglong2* bw = (const ulonglong2*)&s_W1d[k][tx * 32];
#pragma unroll
        for (int m = 0; m < 8; m++) {
            ulonglong2 bv = bw[m];                                  // dup-pairs jj=2m, 2m+1
            ffma2(acc[0][2 * m],     av.x, bv.x);
            ffma2(acc[0][2 * m + 1], av.x, bv.y);
            ffma2(acc[1][2 * m],     av.y, bv.x);
            ffma2(acc[1][2 * m + 1], av.y, bv.y);
        }
    }

    // ---- ReLU ----
#pragma unroll
    for (int p = 0; p < 2; p++)
#pragma unroll
        for (int jj = 0; jj < 16; jj++) {
            float2 v = unpk(acc[p][jj]);
            acc[p][jj] = fpk(fmaxf(v.x, 0.f), fmaxf(v.y, 0.f));
        }

    // ---- GEMM2 partials: out-pairs over c, reduce j within this thread's 16 j ----
    ull oacc[4][8];                                  // [edge][c-pair], c = 2m, 2m+1
#pragma unroll
    for (int e2 = 0; e2 < 4; e2++)
#pragma unroll
        for (int m = 0; m < 8; m++) oacc[e2][m] = 0ull;

#pragma unroll
    for (int jj = 0; jj < 16; jj++) {
        int j = tx * 16 + jj;
        float2 h01 = unpk(acc[0][jj]);
        float2 h23 = unpk(acc[1][jj]);
        ull a0 = fdup(h01.x), a1 = fdup(h01.y);
        ull a2 = fdup(h23.x), a3 = fdup(h23.y);
        const ulonglong2* wr = (const ulonglong2*)&s_W2[j][0];      // natural c-pairs
#pragma unroll
        for (int q = 0; q < 4; q++) {
            ulonglong2 bv = wr[q];                                  // pairs m=2q, 2q+1
            ffma2(oacc[0][2 * q],     a0, bv.x); ffma2(oacc[0][2 * q + 1], a0, bv.y);
            ffma2(oacc[1][2 * q],     a1, bv.x); ffma2(oacc[1][2 * q + 1], a1, bv.y);
            ffma2(oacc[2][2 * q],     a2, bv.x); ffma2(oacc[2][2 * q + 1], a2, bv.y);
            ffma2(oacc[3][2 * q],     a3, bv.x); ffma2(oacc[3][2 * q + 1], a3, bv.y);
        }
    }

    // ---- reduce partial j-sums across the 4 tx lanes (butterfly xor 1, 2) ----
#pragma unroll
    for (int e2 = 0; e2 < 4; e2++)
#pragma unroll
        for (int m = 0; m < 8; m++) {
            ull o = __shfl_xor_sync(0xffffffffu, oacc[e2][m], 1);
            fadd2(oacc[e2][m], o);
        }
#pragma unroll
    for (int e2 = 0; e2 < 4; e2++)
#pragma unroll
        for (int m = 0; m < 8; m++) {
            ull o = __shfl_xor_sync(0xffffffffu, oacc[e2][m], 2);
            fadd2(oacc[e2][m], o);
        }

    // ---- epilogue: +b2, write e_new (float4), scatter via scalar REDG.ADD.F32 ----
    float4 b2v = ((const float4*)b2)[tx];
    ull bb0 = fpk(b2v.x, b2v.y), bb1 = fpk(b2v.z, b2v.w);
#pragma unroll
    for (int e2 = 0; e2 < 4; e2++) {
        ull r0 = oacc[e2][2 * tx];     fadd2(r0, bb0);
        ull r1 = oacc[e2][2 * tx + 1]; fadd2(r1, bb1);
        float2 f0 = unpk(r0), f1 = unpk(r1);
        float4 ov = make_float4(f0.x, f0.y, f1.x, f1.y);
        int eslot = ty * 4 + e2;
        int edge = base + eslot;
        ((float4*)e_out)[edge * 4 + tx] = ov;
        float* ap = g_agg + s_dst[eslot] * 16 + tx * 4;
        atomicAdd(ap + 0, ov.x);
        atomicAdd(ap + 1, ov.y);
        atomicAdd(ap + 2, ov.z);
        atomicAdd(ap + 3, ov.w);
    }
}

// ---------------------------------------------------------------------------
// K3: node MLP  x_new = fO(concat(x, agg)). One node per thread; weights in smem.
// ---------------------------------------------------------------------------
__global__ void __launch_bounds__(256) node_kernel(
    const float* __restrict__ x,
    const float* __restrict__ W1, const float* __restrict__ b1,
    const float* __restrict__ W2, const float* __restrict__ b2,
    float* __restrict__ x_out)
{
    __shared__ float sW1[32 * 64];
    __shared__ float sW2[64 * 16];
    __shared__ float sb1[64];
    __shared__ float sb2[16];
    int tid = threadIdx.x;
#pragma unroll
    for (int r = 0; r < 8; r++) sW1[r * 256 + tid] = W1[r * 256 + tid];
#pragma unroll
    for (int r = 0; r < 4; r++) sW2[r * 256 + tid] = W2[r * 256 + tid];
    if (tid < 64) sb1[tid] = b1[tid];
    if (tid < 16) sb2[tid] = b2[tid];
    __syncthreads();

    int n = blockIdx.x * 256 + tid;
    if (n >= NN) return;

    float in[32];
#pragma unroll
    for (int q = 0; q < 4; q++) {
        float4 v = ((const float4*)x)[n * 4 + q];
        in[q * 4 + 0] = v.x; in[q * 4 + 1] = v.y;
        in[q * 4 + 2] = v.z; in[q * 4 + 3] = v.w;
        float4 a = ((const float4*)g_agg)[n * 4 + q];
        in[16 + q * 4 + 0] = a.x; in[16 + q * 4 + 1] = a.y;
        in[16 + q * 4 + 2] = a.z; in[16 + q * 4 + 3] = a.w;
    }
    float o[16];
#pragma unroll
    for (int c = 0; c < 16; c++) o[c] = sb2[c];
    for (int j = 0; j < 64; j++) {                   // keep j-loop rolled (I-cache)
        float h = sb1[j];
#pragma unroll
        for (int k = 0; k < 32; k++) h = fmaf(in[k], sW1[k * 64 + j], h);
        h = fmaxf(h, 0.f);
#pragma unroll
        for (int c = 0; c < 16; c++) o[c] = fmaf(h, sW2[j * 16 + c], o[c]);
    }
#pragma unroll
    for (int q = 0; q < 4; q++)
        ((float4*)x_out)[n * 4 + q] =
            make_float4(o[q * 4 + 0], o[q * 4 + 1], o[q * 4 + 2], o[q * 4 + 3]);
}

// ---------------------------------------------------------------------------
extern "C" void kernel_launch(void* const* d_in, const int* in_sizes, int n_in,
                              void* d_out, int out_size)
{
    const float* x     = (const float*)d_in[0];
    const int*   ei    = (const int*)d_in[1];    // edge_index: int32 (JAX x64 disabled)
    const float* e     = (const float*)d_in[2];
    const float* fRW1  = (const float*)d_in[3];
    const float* fRb1  = (const float*)d_in[4];
    const float* fRW2  = (const float*)d_in[5];
    const float* fRb2  = (const float*)d_in[6];
    const float* fOW1  = (const float*)d_in[7];
    const float* fOb1  = (const float*)d_in[8];
    const float* fOW2  = (const float*)d_in[9];
    const float* fOb2  = (const float*)d_in[10];

    float* x_new = (float*)d_out;            // [NN, 16]
    float* e_new = x_new + NN * 16;          // [NE, 16]

    zero_agg_kernel<<<(NN * 16 / 4 + 255) / 256, 256>>>();
    precompute_pq<<<(NN * 64) / 256, 256>>>(x, fRW1, fRb1);
    edge_kernel<<<NE / 128, 128>>>(ei, e, fRW1, fRW2, fRb2, e_new);
    node_kernel<<<(NN + 255) / 256, 256>>>(x, fOW1, fOb1, fOW2, fOb2, x_new);
}

// round 7
// speedup vs baseline: 1.8384x; 1.8384x over previous
#include <cuda_runtime.h>
#include <cstdint>

#define NN 50000
#define NE 1600000

// Scratch (static device globals — no allocation in kernel_launch)
__device__ float g_P[NN * 64];     // P[n][j] = fR_b1[j] + sum_k x[n][k] * fR_W1[k][j]      (dst part)
__device__ float g_Q[NN * 64];     // Q[n][j] =            sum_k x[n][k] * fR_W1[16+k][j]   (src part)
__device__ float g_agg[NN * 16];   // scatter-sum of e_new by dst

// ---------------------------------------------------------------------------
// K0: zero the aggregation buffer
// ---------------------------------------------------------------------------
__global__ void zero_agg_kernel() {
    int i = blockIdx.x * 256 + threadIdx.x;
    if (i < NN * 16 / 4) ((float4*)g_agg)[i] = make_float4(0.f, 0.f, 0.f, 0.f);
}

// ---------------------------------------------------------------------------
// K1: per-node precompute  P = x@W1[0:16] + b1,  Q = x@W1[16:32]
// ---------------------------------------------------------------------------
__global__ void __launch_bounds__(256) precompute_pq(
    const float* __restrict__ x, const float* __restrict__ W1,
    const float* __restrict__ b1)
{
    int idx = blockIdx.x * 256 + threadIdx.x;       // exactly NN*64 threads
    int n = idx >> 6, j = idx & 63;
    float p = b1[j], q = 0.f;
#pragma unroll
    for (int k = 0; k < 16; k++) {
        float xv = __ldg(x + n * 16 + k);           // broadcast within warp
        p = fmaf(xv, W1[k * 64 + j], p);
        q = fmaf(xv, W1[(16 + k) * 64 + j], q);
    }
    g_P[idx] = p;
    g_Q[idx] = q;
}

// ---------------------------------------------------------------------------
// K2: edge kernel. 64 edges/block, 128 threads = 32 edge-rows (2 edges each)
//     x 4 hidden col-groups (16 j each). Scalar fp32; LDS-optimized layouts:
//   s_W1x[k][q][tx][4]  — per-(k,q) LDS.128 hits banks tx*4..tx*4+3: conflict-free
//   s_W2x[jj][cq][tx][4] — same trick for GEMM2: conflict-free
//   s_E[edge][20]       — e rows, pad 20 keeps 16B align, <=2-way conflict
// ---------------------------------------------------------------------------
__global__ void __launch_bounds__(128) edge_kernel(
    const int* __restrict__ ei, const float* __restrict__ e_in,
    const float* __restrict__ W1, const float* __restrict__ W2,
    const float* __restrict__ b2, float* __restrict__ e_out)
{
    __shared__ __align__(16) float s_E[64][20];     // 5120 B
    __shared__ __align__(16) float s_W1x[1024];     // [k][q][tx][i] = W1c[k][tx*16+q*4+i]
    __shared__ __align__(16) float s_W2x[1024];     // [jj][cq][tx][i] = W2[tx*16+jj][cq*4+i]
    __shared__ float s_b2[16];

    const int tid = threadIdx.x;
    const int tx = tid & 3;          // hidden col-group (16 j each)
    const int ty = tid >> 2;         // edge-row (2 edges each)
    const int base = blockIdx.x * 64;
    const int e0 = ty * 2, e1 = e0 + 1;

    // ---- indices for this thread's 2 edges (int32; tx-duplicated, HW dedups) ----
    const int s0 = ei[base + e0];
    const int s1 = ei[base + e1];
    const int d0 = ei[NE + base + e0];
    const int d1 = ei[NE + base + e1];

    // ---- gather-add P[dst]+Q[src] into acc (issued before staging: latency
    //      hides under the smem fill below) ----
    float acc[2][16];
#pragma unroll
    for (int q = 0; q < 4; q++) {
        float4 p0 = *((const float4*)(g_P + d0 * 64 + tx * 16) + q);
        float4 q0 = *((const float4*)(g_Q + s0 * 64 + tx * 16) + q);
        float4 p1 = *((const float4*)(g_P + d1 * 64 + tx * 16) + q);
        float4 q1 = *((const float4*)(g_Q + s1 * 64 + tx * 16) + q);
        acc[0][q * 4 + 0] = p0.x + q0.x;  acc[0][q * 4 + 1] = p0.y + q0.y;
        acc[0][q * 4 + 2] = p0.z + q0.z;  acc[0][q * 4 + 3] = p0.w + q0.w;
        acc[1][q * 4 + 0] = p1.x + q1.x;  acc[1][q * 4 + 1] = p1.y + q1.y;
        acc[1][q * 4 + 2] = p1.z + q1.z;  acc[1][q * 4 + 3] = p1.w + q1.w;
    }

    // ---- stage e tile: 64 edges x 16 floats = 256 float4, row layout ----
#pragma unroll
    for (int r = 0; r < 2; r++) {
        int idx = r * 128 + tid;                     // 0..255
        float4 v = ((const float4*)e_in)[base * 4 + idx];
        *(float4*)&s_E[idx >> 2][(idx & 3) * 4] = v;
    }
    // ---- stage W1c interleaved: s_W1x[k*64 + q*16 + txx*4 + i] = W1c[k][txx*16+q*4+i] ----
#pragma unroll
    for (int r = 0; r < 8; r++) {
        int t = r * 128 + tid;                       // 0..1023
        int k = t >> 6, rem = t & 63;
        int q = rem >> 4, txx = (rem >> 2) & 3, i = rem & 3;
        s_W1x[t] = W1[(32 + k) * 64 + txx * 16 + q * 4 + i];
    }
    // ---- stage W2 interleaved: s_W2x[jj*64 + cq*16 + txx*4 + i] = W2[txx*16+jj][cq*4+i] ----
#pragma unroll
    for (int r = 0; r < 8; r++) {
        int t = r * 128 + tid;                       // 0..1023
        int jj = t >> 6, rem = t & 63;
        int cq = rem >> 4, txx = (rem >> 2) & 3, i = rem & 3;
        s_W2x[t] = W2[(txx * 16 + jj) * 16 + cq * 4 + i];
    }
    if (tid < 16) s_b2[tid] = b2[tid];
    __syncthreads();

    // ---- GEMM1: acc += e @ W1c  (k in chunks of 4; vector LDS only) ----
#pragma unroll
    for (int k4 = 0; k4 < 4; k4++) {
        float4 a0 = *(const float4*)&s_E[e0][k4 * 4];
        float4 a1 = *(const float4*)&s_E[e1][k4 * 4];
        const float av0[4] = {a0.x, a0.y, a0.z, a0.w};
        const float av1[4] = {a1.x, a1.y, a1.z, a1.w};
#pragma unroll
        for (int kk = 0; kk < 4; kk++) {
            int k = k4 * 4 + kk;
            float e0v = av0[kk], e1v = av1[kk];
#pragma unroll
            for (int q = 0; q < 4; q++) {
                float4 w = *(const float4*)&s_W1x[k * 64 + q * 16 + tx * 4];
                acc[0][q * 4 + 0] = fmaf(e0v, w.x, acc[0][q * 4 + 0]);
                acc[0][q * 4 + 1] = fmaf(e0v, w.y, acc[0][q * 4 + 1]);
                acc[0][q * 4 + 2] = fmaf(e0v, w.z, acc[0][q * 4 + 2]);
                acc[0][q * 4 + 3] = fmaf(e0v, w.w, acc[0][q * 4 + 3]);
                acc[1][q * 4 + 0] = fmaf(e1v, w.x, acc[1][q * 4 + 0]);
                acc[1][q * 4 + 1] = fmaf(e1v, w.y, acc[1][q * 4 + 1]);
                acc[1][q * 4 + 2] = fmaf(e1v, w.z, acc[1][q * 4 + 2]);
                acc[1][q * 4 + 3] = fmaf(e1v, w.w, acc[1][q * 4 + 3]);
            }
        }
    }

    // ---- ReLU ----
#pragma unroll
    for (int p = 0; p < 2; p++)
#pragma unroll
        for (int jj = 0; jj < 16; jj++)
            acc[p][jj] = fmaxf(acc[p][jj], 0.f);

    // ---- GEMM2 partials: this thread's 16 j (j = tx*16+jj) -> all 16 c ----
    float oacc[2][16];
#pragma unroll
    for (int p = 0; p < 2; p++)
#pragma unroll
        for (int c = 0; c < 16; c++) oacc[p][c] = 0.f;

#pragma unroll
    for (int jj = 0; jj < 16; jj++) {
        float h0 = acc[0][jj];
        float h1 = acc[1][jj];
#pragma unroll
        for (int cq = 0; cq < 4; cq++) {
            float4 w = *(const float4*)&s_W2x[jj * 64 + cq * 16 + tx * 4];
            oacc[0][cq * 4 + 0] = fmaf(h0, w.x, oacc[0][cq * 4 + 0]);
            oacc[0][cq * 4 + 1] = fmaf(h0, w.y, oacc[0][cq * 4 + 1]);
            oacc[0][cq * 4 + 2] = fmaf(h0, w.z, oacc[0][cq * 4 + 2]);
            oacc[0][cq * 4 + 3] = fmaf(h0, w.w, oacc[0][cq * 4 + 3]);
            oacc[1][cq * 4 + 0] = fmaf(h1, w.x, oacc[1][cq * 4 + 0]);
            oacc[1][cq * 4 + 1] = fmaf(h1, w.y, oacc[1][cq * 4 + 1]);
            oacc[1][cq * 4 + 2] = fmaf(h1, w.z, oacc[1][cq * 4 + 2]);
            oacc[1][cq * 4 + 3] = fmaf(h1, w.w, oacc[1][cq * 4 + 3]);
        }
    }

    // ---- reduce partial j-sums across the 4 tx lanes (butterfly xor 1, 2) ----
#pragma unroll
    for (int p = 0; p < 2; p++)
#pragma unroll
        for (int c = 0; c < 16; c++) {
            float v = oacc[p][c];
            v += __shfl_xor_sync(0xffffffffu, v, 1);
            v += __shfl_xor_sync(0xffffffffu, v, 2);
            oacc[p][c] = v;
        }

    // ---- epilogue: +b2, write e_new (float4 per lane), scatter scalar atomics ----
#pragma unroll
    for (int p = 0; p < 2; p++) {
        int edge = base + e0 + p;
        int dst = (p == 0) ? d0 : d1;
        float4 ov;
        ov.x = oacc[p][tx * 4 + 0] + s_b2[tx * 4 + 0];
        ov.y = oacc[p][tx * 4 + 1] + s_b2[tx * 4 + 1];
        ov.z = oacc[p][tx * 4 + 2] + s_b2[tx * 4 + 2];
        ov.w = oacc[p][tx * 4 + 3] + s_b2[tx * 4 + 3];
        ((float4*)e_out)[edge * 4 + tx] = ov;
        float* ap = g_agg + dst * 16 + tx * 4;
        atomicAdd(ap + 0, ov.x);
        atomicAdd(ap + 1, ov.y);
        atomicAdd(ap + 2, ov.z);
        atomicAdd(ap + 3, ov.w);
    }
}

// ---------------------------------------------------------------------------
// K3: node MLP  x_new = fO(concat(x, agg)). One node per thread; weights in smem.
// 128-thread blocks: 391 blocks (was 196 — grid-limited).
// ---------------------------------------------------------------------------
__global__ void __launch_bounds__(128) node_kernel(
    const float* __restrict__ x,
    const float* __restrict__ W1, const float* __restrict__ b1,
    const float* __restrict__ W2, const float* __restrict__ b2,
    float* __restrict__ x_out)
{
    __shared__ float sW1[32 * 64];
    __shared__ float sW2[64 * 16];
    __shared__ float sb1[64];
    __shared__ float sb2[16];
    int tid = threadIdx.x;
#pragma unroll
    for (int r = 0; r < 16; r++) sW1[r * 128 + tid] = W1[r * 128 + tid];
#pragma unroll
    for (int r = 0; r < 8; r++) sW2[r * 128 + tid] = W2[r * 128 + tid];
    if (tid < 64) sb1[tid] = b1[tid];
    if (tid < 16) sb2[tid] = b2[tid];
    __syncthreads();

    int n = blockIdx.x * 128 + tid;
    if (n >= NN) return;

    float in[32];
#pragma unroll
    for (int q = 0; q < 4; q++) {
        float4 v = ((const float4*)x)[n * 4 + q];
        in[q * 4 + 0] = v.x; in[q * 4 + 1] = v.y;
        in[q * 4 + 2] = v.z; in[q * 4 + 3] = v.w;
        float4 a = ((const float4*)g_agg)[n * 4 + q];
        in[16 + q * 4 + 0] = a.x; in[16 + q * 4 + 1] = a.y;
        in[16 + q * 4 + 2] = a.z; in[16 + q * 4 + 3] = a.w;
    }
    float o[16];
#pragma unroll
    for (int c = 0; c < 16; c++) o[c] = sb2[c];
    for (int j = 0; j < 64; j++) {                   // keep j-loop rolled (I-cache)
        float h = sb1[j];
#pragma unroll
        for (int k = 0; k < 32; k++) h = fmaf(in[k], sW1[k * 64 + j], h);
        h = fmaxf(h, 0.f);
#pragma unroll
        for (int c = 0; c < 16; c++) o[c] = fmaf(h, sW2[j * 16 + c], o[c]);
    }
#pragma unroll
    for (int q = 0; q < 4; q++)
        ((float4*)x_out)[n * 4 + q] =
            make_float4(o[q * 4 + 0], o[q * 4 + 1], o[q * 4 + 2], o[q * 4 + 3]);
}

// ---------------------------------------------------------------------------
extern "C" void kernel_launch(void* const* d_in, const int* in_sizes, int n_in,
                              void* d_out, int out_size)
{
    const float* x     = (const float*)d_in[0];
    const int*   ei    = (const int*)d_in[1];    // edge_index: int32 (JAX x64 disabled)
    const float* e     = (const float*)d_in[2];
    const float* fRW1  = (const float*)d_in[3];
    const float* fRb1  = (const float*)d_in[4];
    const float* fRW2  = (const float*)d_in[5];
    const float* fRb2  = (const float*)d_in[6];
    const float* fOW1  = (const float*)d_in[7];
    const float* fOb1  = (const float*)d_in[8];
    const float* fOW2  = (const float*)d_in[9];
    const float* fOb2  = (const float*)d_in[10];

    float* x_new = (float*)d_out;            // [NN, 16]
    float* e_new = x_new + NN * 16;          // [NE, 16]

    zero_agg_kernel<<<(NN * 16 / 4 + 255) / 256, 256>>>();
    precompute_pq<<<(NN * 64) / 256, 256>>>(x, fRW1, fRb1);
    edge_kernel<<<NE / 64, 128>>>(ei, e, fRW1, fRW2, fRb2, e_new);
    node_kernel<<<(NN + 127) / 128, 128>>>(x, fOW1, fOb1, fOW2, fOb2, x_new);
}